// round 17
// baseline (speedup 1.0000x reference)
#include <cuda_runtime.h>
#include <cuda_fp16.h>
#include <math.h>

#define WIN   11
#define RAD   5

// ---- K1 (h-blur): full-width row strips ----
#define K1ROWS   16
#define K1W      522           // 512 + 2*RAD
#define K1PITCH  523           // uint2 units (odd-ish -> CF 16-row walk)
#define K1THREADS 256

// ---- K2 (v-blur + SSIM): 32x40 tiles ----
#define TS2Y   40
#define ST2    50              // staged rows (TS2Y + 2*RAD)
#define PHB2   33              // ull2 pitch (odd -> CF)
#define K2THREADS 256
#define NY2    13              // ceil(512/40)
#define NBLOCKS2 (16 * NY2 * 48)

#define C1 0.0001f
#define C2 0.0009f

struct GW { float g[WIN]; };

typedef unsigned long long f2_t;
__device__ __forceinline__ f2_t pack2(float lo, float hi) {
    f2_t r; asm("mov.b64 %0, {%1, %2};" : "=l"(r) : "f"(lo), "f"(hi)); return r;
}
__device__ __forceinline__ void unpack2(f2_t v, float& lo, float& hi) {
    asm("mov.b64 {%0, %1}, %2;" : "=f"(lo), "=f"(hi) : "l"(v));
}
__device__ __forceinline__ void fma2(f2_t& d, f2_t a, f2_t b) {
    asm("fma.rn.f32x2 %0, %1, %2, %0;" : "+l"(d) : "l"(a), "l"(b));
}
__device__ __forceinline__ f2_t mul2(f2_t a, f2_t b) {
    f2_t r; asm("mul.rn.f32x2 %0, %1, %2;" : "=l"(r) : "l"(a), "l"(b)); return r;
}

// ---- scratch: h-blurred fields, x-major [img][x][y], 16B/px each ----
#define NPX (48u * 512u * 512u)
__device__ ulonglong2 g_hb0[NPX];   // (AB, AABB)
__device__ ulonglong2 g_hb1[NPX];   // (AFBF, FFF)
__device__ float        g_partials[NBLOCKS2];
__device__ unsigned int g_done = 0;

__device__ __forceinline__ float ssim_val(float mu1, float mu2,
                                          float e11, float e22, float e12) {
    float mu1sq = mu1 * mu1;
    float mu2sq = mu2 * mu2;
    float mu12  = mu1 * mu2;
    float num = (2.0f * mu12 + C1) * (2.0f * (e12 - mu12) + C2);
    float den = (mu1sq + mu2sq + C1) * ((e11 - mu1sq) + (e22 - mu2sq) + C2);
    return __fdividef(num, den);
}

#define GSYM(k) gg[(k) < 6 ? (k) : 10 - (k)]

// ============ K1: horizontal blur, rows -> g_hb0/g_hb1 (x-major) ============
#define K1_SMEM (K1ROWS * K1PITCH * 8)   // 66944 B

__global__ __launch_bounds__(K1THREADS, 3)
void ssim_hpass_kernel(const float* __restrict__ A,
                       const float* __restrict__ B,
                       const float* __restrict__ F,
                       GW gw) {
    extern __shared__ float sm[];
    uint2* sR = (uint2*)sm;

    const int tid = threadIdx.x;
    const int img = blockIdx.y;
    const int y0  = blockIdx.x * K1ROWS;
    const int pbase = img * (512 * 512);

    f2_t gg[6];
    #pragma unroll
    for (int k = 0; k < 6; k++) gg[k] = pack2(gw.g[k], gw.g[k]);

    // stage 16 rows x 522 cols as fp16x4 (A,B)|(F,F^2); x zero-padded
    for (int i = tid; i < K1ROWS * K1W; i += K1THREADS) {
        int r = i / K1W;
        int c = i - r * K1W;
        int gx = c - RAD;
        float a = 0.f, b = 0.f, f = 0.f;
        if ((unsigned)gx < 512u) {
            int off = pbase + (y0 + r) * 512 + gx;
            a = A[off]; b = B[off]; f = F[off];
        }
        __half2 hab = __floats2half2_rn(a, b);
        __half2 hff = __floats2half2_rn(f, f * f);
        uint2 st;
        st.x = *reinterpret_cast<unsigned*>(&hab);
        st.y = *reinterpret_cast<unsigned*>(&hff);
        sR[r * K1PITCH + c] = st;
    }
    __syncthreads();

    // h-pass: 16 rows x 128 groups of 4 outputs = 2048 items = 8 rounds
    #pragma unroll 1
    for (int round = 0; round < 8; round++) {
        int r = tid & 15;                       // lanes walk rows (CF)
        int g = (tid >> 4) + 16 * round;        // 0..127
        int c0 = g << 2;
        const uint2* p = sR + r * K1PITCH + c0;

        f2_t aAB[4]   = {0, 0, 0, 0};
        f2_t aAABB[4] = {0, 0, 0, 0};
        f2_t aAFBF[4] = {0, 0, 0, 0};
        f2_t aFFF[4]  = {0, 0, 0, 0};

        #pragma unroll
        for (int ii = 0; ii < 14; ii++) {
            uint2 v = p[ii];
            __half2 habh = *reinterpret_cast<__half2*>(&v.x);
            __half2 hffh = *reinterpret_cast<__half2*>(&v.y);
            float2 abf  = __half22float2(habh);
            float2 fff2 = __half22float2(hffh);
            f2_t ab   = pack2(abf.x, abf.y);
            f2_t ff2  = pack2(fff2.x, fff2.y);
            f2_t ffp  = pack2(fff2.x, fff2.x);
            f2_t aabb = mul2(ab, ab);
            f2_t afbf = mul2(ab, ffp);
            #pragma unroll
            for (int j = 0; j < 4; j++) {
                int k = ii - j;
                if (k >= 0 && k < WIN) {
                    fma2(aAB[j],   GSYM(k), ab);
                    fma2(aAABB[j], GSYM(k), aabb);
                    fma2(aAFBF[j], GSYM(k), afbf);
                    fma2(aFFF[j],  GSYM(k), ff2);
                }
            }
        }
        int y = y0 + r;
        #pragma unroll
        for (int j = 0; j < 4; j++) {
            int idx = (img * 512 + c0 + j) * 512 + y;   // x-major
            g_hb0[idx] = make_ulonglong2(aAB[j],   aAABB[j]);
            g_hb1[idx] = make_ulonglong2(aAFBF[j], aFFF[j]);
        }
    }
}

// ============ K2: vertical blur + SSIM + global reduction ============
#define OFF2_S1  (ST2 * PHB2 * 4)           // floats (ull2 = 4 floats)
#define OFF2_RED (2 * ST2 * PHB2 * 4)
#define K2_SMEM  ((OFF2_RED + 16) * 4)      // 52864 B

__global__ __launch_bounds__(K2THREADS, 4)
void ssim_vpass_kernel(GW gw, float* __restrict__ out) {
    extern __shared__ float sm[];
    ulonglong2* s0  = (ulonglong2*)sm;
    ulonglong2* s1  = (ulonglong2*)(sm + OFF2_S1);
    float*      red = sm + OFF2_RED;

    const int tid = threadIdx.x;
    const int img = 47 - blockIdx.z;        // reverse: catch K1 tail in L2
    const int x0  = blockIdx.x * 32;
    const int yt  = blockIdx.y * TS2Y;

    f2_t gg[6];
    #pragma unroll
    for (int k = 0; k < 6; k++) gg[k] = pack2(gw.g[k], gw.g[k]);

    // stage 32 cols x 50 rows of hb0+hb1 (y-contiguous gmem -> coalesced)
    {
        int xc   = tid >> 3;                 // 0..31
        int ysub = tid & 7;
        int colbase = (img * 512 + x0 + xc) * 512;
        #pragma unroll
        for (int k = 0; k < 7; k++) {
            int yi = ysub + 8 * k;
            if (yi < ST2) {
                int yg = yt - RAD + yi;
                ulonglong2 v0 = make_ulonglong2(0, 0);
                ulonglong2 v1 = make_ulonglong2(0, 0);
                if ((unsigned)yg < 512u) {
                    v0 = g_hb0[colbase + yg];
                    v1 = g_hb1[colbase + yg];
                }
                s0[yi * PHB2 + xc] = v0;
                s1[yi * PHB2 + xc] = v1;
            }
        }
    }
    __syncthreads();

    // v-pass: 8 warps x 5 rows = 40 = TS2Y exactly
    const int vc = tid & 31;
    const int r0 = (tid >> 5) * 5;           // 0,5,...,35; max read 35+14=49

    f2_t vAB[5], vAABB[5], vAFBF[5], vFFF[5];
    #pragma unroll
    for (int j = 0; j < 5; j++) { vAB[j]=0; vAABB[j]=0; vAFBF[j]=0; vFFF[j]=0; }

    #pragma unroll
    for (int ii = 0; ii < 15; ii++) {
        int o = (r0 + ii) * PHB2 + vc;
        ulonglong2 h0 = s0[o];
        ulonglong2 h1 = s1[o];
        #pragma unroll
        for (int j = 0; j < 5; j++) {
            int k = ii - j;
            if (k >= 0 && k < WIN) {
                fma2(vAB[j],   GSYM(k), h0.x);
                fma2(vAABB[j], GSYM(k), h0.y);
                fma2(vAFBF[j], GSYM(k), h1.x);
                fma2(vFFF[j],  GSYM(k), h1.y);
            }
        }
    }

    float local = 0.f;
    #pragma unroll
    for (int j = 0; j < 5; j++) {
        if (yt + r0 + j < 512) {
            float muA, muB, eAA, eBB, eAF, eBF, muF, eFF;
            unpack2(vAB[j],   muA, muB);
            unpack2(vAABB[j], eAA, eBB);
            unpack2(vAFBF[j], eAF, eBF);
            unpack2(vFFF[j],  muF, eFF);
            local += ssim_val(muA, muF, eAA, eFF, eAF);
            local += ssim_val(muB, muF, eBB, eFF, eBF);
        }
    }

    // block reduction (8 warps)
    #pragma unroll
    for (int o = 16; o > 0; o >>= 1)
        local += __shfl_down_sync(0xffffffffu, local, o);
    if ((tid & 31) == 0) red[tid >> 5] = local;
    __syncthreads();

    const int bid = blockIdx.x + 16 * blockIdx.y + (16 * NY2) * blockIdx.z;
    __shared__ bool is_last;
    if (tid == 0) {
        float v = 0.f;
        #pragma unroll
        for (int w = 0; w < 8; w++) v += red[w];
        g_partials[bid] = v;
        __threadfence();
        unsigned int old = atomicAdd(&g_done, 1u);
        is_last = (old == NBLOCKS2 - 1);
    }
    __syncthreads();

    if (is_last) {
        double s = 0.0;
        for (int i = tid; i < NBLOCKS2; i += K2THREADS)
            s += (double)__ldcg(&g_partials[i]);
        #pragma unroll
        for (int o = 16; o > 0; o >>= 1)
            s += __shfl_down_sync(0xffffffffu, s, o);
        double* redd = (double*)red;
        if ((tid & 31) == 0) redd[tid >> 5] = s;
        __syncthreads();
        if (tid == 0) {
            double t = 0.0;
            #pragma unroll
            for (int w = 0; w < 8; w++) t += redd[w];
            out[0] = (float)(0.5 * t / 12582912.0);
            g_done = 0;
        }
    }
}

extern "C" void kernel_launch(void* const* d_in, const int* in_sizes, int n_in,
                              void* d_out, int out_size) {
    const float* A = (const float*)d_in[0];
    const float* B = (const float*)d_in[1];
    const float* F = (const float*)d_in[2];

    GW gw;
    double gd[WIN], s = 0.0;
    for (int i = 0; i < WIN; i++) {
        double d = (double)(i - RAD);
        gd[i] = exp(-(d * d) / (2.0 * 1.5 * 1.5));
        s += gd[i];
    }
    for (int i = 0; i < WIN; i++) gw.g[i] = (float)(gd[i] / s);

    cudaFuncSetAttribute(ssim_hpass_kernel,
                         cudaFuncAttributeMaxDynamicSharedMemorySize, K1_SMEM);
    cudaFuncSetAttribute(ssim_vpass_kernel,
                         cudaFuncAttributeMaxDynamicSharedMemorySize, K2_SMEM);

    dim3 g1(512 / K1ROWS, 48);
    ssim_hpass_kernel<<<g1, K1THREADS, K1_SMEM>>>(A, B, F, gw);

    dim3 g2(16, NY2, 48);
    ssim_vpass_kernel<<<g2, K2THREADS, K2_SMEM>>>(gw, (float*)d_out);
}